// round 10
// baseline (speedup 1.0000x reference)
#include <cuda_runtime.h>
#include <cstdint>

// ---------------- problem constants ----------------
#define BB   16
#define DD   64
#define HH   768
#define NE   7
#define ROWS (BB*DD)                 // 1024 utterances
#define PAIRS_PER_B (DD*(DD+1)/2)    // 2080
#define NPAIR (BB*PAIRS_PER_B)       // 33280
#define FOLD_TASKS (2*1552)          // 3104
#define TOTAL_TASKS (FOLD_TASKS + 16 + 65)  // 3185

#define GRID  256
#define NTHR  256
#define TOTW  (GRID*NTHR/32)         // 2048 warps

// ---------------- device scratch (no allocs allowed) ----------------
__device__ float g_Ob[4];             // folded expert bias [e*2+c]
__device__ float g_W19[19*HH];        // SoA packed weights [m][j]
__device__ float g_Tail[12*8];        // tail weights for f=768..775
__device__ float g_T[ROWS*12];        // per-utterance table
__device__ float g_spk[ROWS];         // speaker ids as float
__device__ unsigned short g_pairidx[PAIRS_PER_B]; // packed (end<<8)|t
__device__ unsigned int g_bar;        // grid barrier counter (monotonic)
__device__ unsigned int g_cnt[BB];    // per-batch sync counters (monotonic)

// ---- phase-A warp task dispatcher (one task per call) ----
__device__ __forceinline__ void do_task(int task, int lane,
            const void*  __restrict__ spk_raw,
            const float* __restrict__ emo_w,
            const float* __restrict__ gate_w,
            const float* __restrict__ w1,
            const float* __restrict__ b1,
            const float* __restrict__ w2,
            const float* __restrict__ b2) {
    if (task < FOLD_TASKS) {
        const int e = task / 1552, j = task - e * 1552;
        const float4* a4  = (const float4*)(w1 + ((size_t)(e * 1552 + j)) * 256);
        const float4* wb4 = (const float4*)(w2 + e * 512);
        float4 x0 = a4[lane];
        float4 x1 = a4[lane + 32];
        float4 p0 = wb4[2 * lane];
        float4 p1 = wb4[2 * lane + 1];
        float4 p2 = wb4[64 + 2 * lane];
        float4 p3 = wb4[65 + 2 * lane];
        float a0 = x0.x*p0.x + x0.y*p0.z + x0.z*p1.x + x0.w*p1.z
                 + x1.x*p2.x + x1.y*p2.z + x1.z*p3.x + x1.w*p3.z;
        float a1 = x0.x*p0.y + x0.y*p0.w + x0.z*p1.y + x0.w*p1.w
                 + x1.x*p2.y + x1.y*p2.w + x1.z*p3.y + x1.w*p3.w;
        #pragma unroll
        for (int off = 16; off; off >>= 1) {
            a0 += __shfl_down_sync(0xffffffffu, a0, off);
            a1 += __shfl_down_sync(0xffffffffu, a1, off);
        }
        if (lane == 0) {
            if (j < HH) {                          // -> O1 (m = 11+e*2+c)
                g_W19[(11 + e * 2) * HH + j] = a0;
                g_W19[(12 + e * 2) * HH + j] = a1;
            } else if (j < 776) {                  // tail O1: m = 4+e*2+c
                g_Tail[(4 + e * 2) * 8 + (j - HH)] = a0;
                g_Tail[(5 + e * 2) * 8 + (j - HH)] = a1;
            } else if (j < 776 + HH) {             // -> O2 (m = 15+e*2+c)
                int jj = j - 776;
                g_W19[(15 + e * 2) * HH + jj] = a0;
                g_W19[(16 + e * 2) * HH + jj] = a1;
            } else {                               // tail O2: m = 8+e*2+c
                g_Tail[(8 + e * 2) * 8 + (j - 776 - HH)] = a0;
                g_Tail[(9 + e * 2) * 8 + (j - 776 - HH)] = a1;
            }
        }
    } else if (task < FOLD_TASKS + 4) {
        const int idx = task - FOLD_TASKS;        // 0..3
        const int e = idx >> 1, c = idx & 1;
        float s = 0.f;
        for (int k = lane; k < 256; k += 32)
            s += b1[e * 256 + k] * w2[e * 512 + k * 2 + c];
        #pragma unroll
        for (int off = 16; off; off >>= 1)
            s += __shfl_down_sync(0xffffffffu, s, off);
        if (lane == 0) g_Ob[idx] = s + b2[e * 2 + c];
    } else if (task == FOLD_TASKS + 4) {
        // speaker_ids stored int64 or int32 (values in {0,1}).
        const unsigned int* u = (const unsigned int*)spk_raw;
        unsigned nz = 0;
        for (int i = lane; i < ROWS; i += 32) nz |= u[2 * i + 1];
        unsigned any = __ballot_sync(0xffffffffu, nz != 0u);
        const bool w64 = (any == 0u);
        for (int i = lane; i < ROWS; i += 32)
            g_spk[i] = (float)(w64 ? u[2 * i] : u[i]);
    } else if (task < FOLD_TASKS + 16) {
        // pack emo (5376) + G1 (1536) + G2 (1536) + gate tail (32) = 8480
        const int pid = task - (FOLD_TASKS + 5);  // 0..10
        for (int idx = pid * 32 + lane; idx < 8480; idx += 11 * 32) {
            if (idx < 5376) {
                int c = idx / HH, j = idx - c * HH;
                g_W19[c * HH + j] = emo_w[j * 7 + c];
            } else if (idx < 5376 + 1536) {
                int q = idx - 5376;
                int c = q / HH, j = q - c * HH;
                g_W19[(7 + c) * HH + j] = gate_w[j * 2 + c];
            } else if (idx < 5376 + 3072) {
                int q = idx - 5376 - 1536;
                int c = q / HH, j = q - c * HH;
                g_W19[(9 + c) * HH + j] = gate_w[(776 + j) * 2 + c];
            } else {
                int q = idx - 5376 - 3072;        // 0..31
                int m = q >> 3, f8 = q & 7;
                int f = HH + f8;
                float v = (m < 2) ? gate_w[f * 2 + m]
                                  : gate_w[(776 + f) * 2 + (m - 2)];
                g_Tail[m * 8 + f8] = v;
            }
        }
    } else if (task < TOTAL_TASKS) {
        // pair index LUT
        const int q = (task - (FOLD_TASKS + 16)) * 32 + lane;
        if (q < PAIRS_PER_B) {
            int end = (int)((sqrtf(8.f * (float)q + 1.f) - 1.f) * 0.5f);
            while ((end + 1) * (end + 2) / 2 <= q) end++;
            while (end * (end + 1) / 2 > q) end--;
            int t = q - end * (end + 1) / 2;
            g_pairidx[q] = (unsigned short)((end << 8) | t);
        }
    }
}

// ================= fused kernel: prep | grid-barrier | table | pairs ========
__global__ void __launch_bounds__(NTHR, 2)
fused_kernel(const float* __restrict__ pooled,
             const void*  __restrict__ spk_raw,
             const float* __restrict__ emo_w,
             const float* __restrict__ emo_b,
             const float* __restrict__ gate_w,
             const float* __restrict__ gate_b,
             const float* __restrict__ w1,
             const float* __restrict__ b1,
             const float* __restrict__ w2,
             const float* __restrict__ b2,
             float* __restrict__ out_emo,     // [1024*7]
             float* __restrict__ out_cause) { // [33280*2]
    const int tid  = threadIdx.x;
    const int lane = tid & 31;
    const int warp = tid >> 5;
    const int base = blockIdx.x * 4;              // first table row
    const int b    = blockIdx.x >> 4;             // batch
    const int s    = blockIdx.x & 15;             // pair slice

    __shared__ float sp[4][2][20];                // [row_in_block][jchunk][m]

    // ================= phase A: prep tasks (<=2 per warp) ====================
    {
        const int gwarp = blockIdx.x * 8 + warp;  // 0..2047
        do_task(gwarp, lane, spk_raw, emo_w, gate_w, w1, b1, w2, b2);
        const int t2 = gwarp + TOTW;              // 2048..4095
        if (t2 < TOTAL_TASKS)
            do_task(t2, lane, spk_raw, emo_w, gate_w, w1, b1, w2, b2);
    }

    // ---- prefetch x rows (DRAM) before the barrier: latency hidden by wait --
    const int trow = warp >> 1;                   // 0..3
    const int jh   = warp & 1;                    // 0..1
    const int ti   = base + trow;
    float4 x[3];
    {
        const float4* r = (const float4*)(pooled + (size_t)ti * HH);
        #pragma unroll
        for (int u = 0; u < 3; u++)
            x[u] = r[jh * 96 + u * 32 + lane];
    }

    // ================= grid barrier (monotonic ticket) =======================
    __syncthreads();
    if (tid == 0) {
        __threadfence();
        unsigned t = atomicAdd(&g_bar, 1u) + 1u;
        unsigned round_end = ((t + GRID - 1u) / GRID) * GRID;
        volatile unsigned int* c = &g_bar;
        while (*c < round_end) { __nanosleep(64); }
        __threadfence();
    }
    __syncthreads();

    // ================= phase B: table (1 row x 2 j-chunks per warp) =========
    {
        float acc[19];
        #pragma unroll
        for (int m = 0; m < 19; m++) acc[m] = 0.f;

        #pragma unroll
        for (int u = 0; u < 3; u++) {
            const int k = jh * 96 + u * 32 + lane;
            const float4 v = x[u];
            #pragma unroll
            for (int m = 0; m < 19; m++) {
                float4 w = *((const float4*)(g_W19 + m * HH) + k);
                acc[m] += v.x*w.x + v.y*w.y + v.z*w.z + v.w*w.w;
            }
        }

        #pragma unroll
        for (int off = 16; off; off >>= 1) {
            #pragma unroll
            for (int m = 0; m < 19; m++)
                acc[m] += __shfl_down_sync(0xffffffffu, acc[m], off);
        }
        if (lane == 0) {
            #pragma unroll
            for (int m = 0; m < 19; m++)
                sp[trow][jh][m] = acc[m];
        }
    }
    __syncthreads();

    // ---- finalize: warps 0-3, one row each, lanes = m ----
    if (warp < 4) {
        const int row = warp;
        const int i = base + row;
        float sacc = 0.f;
        if (lane < 19)
            sacc = sp[row][0][lane] + sp[row][1][lane];
        float ep = (lane < 7) ? sacc + emo_b[lane] : 0.f;

        // convergent broadcasts (all 32 lanes execute the same shfls)
        float epv[7];
        #pragma unroll
        for (int f8 = 0; f8 < 7; f8++)
            epv[f8] = __shfl_sync(0xffffffffu, ep, f8);

        if (lane < 7)
            out_emo[(size_t)i * 7 + lane] = ep;
        else if (lane < 19) {
            const int m = lane - 7;               // T column 0..11
            float v = sacc;
            #pragma unroll
            for (int f8 = 0; f8 < 7; f8++)
                v += epv[f8] * g_Tail[m * 8 + f8];
            v += g_spk[i] * g_Tail[m * 8 + 7];
            g_T[i * 12 + m] = v;
        }
    }

    // ---- per-batch sync (monotonic ticket; 16 blocks per counter) ----
    __syncthreads();
    if (tid == 0) {
        __threadfence();
        unsigned t = atomicAdd(&g_cnt[b], 1u) + 1u;
        unsigned round_end = ((t + 15u) / 16u) * 16u;
        volatile unsigned int* c = &g_cnt[b];
        while (*c < round_end) { __nanosleep(32); }
        __threadfence();
    }
    __syncthreads();

    // ---- pair phase: 130 pairs per block via LUT ----
    if (tid < 130) {
        const float gb0 = gate_b[0];
        const float gb1 = gate_b[1];
        const float ob0 = g_Ob[0], ob1 = g_Ob[1], ob2 = g_Ob[2], ob3 = g_Ob[3];
        const float* Tb = g_T + b * DD * 12;

        const int q = s * 130 + tid;              // 0..2079 within batch
        const unsigned pe = g_pairidx[q];
        const int end = pe >> 8;
        const int t   = pe & 255;

        const float* Tt = Tb + t   * 12;
        const float* Te = Tb + end * 12;

        float g0 = Tt[0] + Te[2] + gb0;
        float g1 = Tt[1] + Te[3] + gb1;

        float o00 = Tt[4] + Te[8]  + ob0;
        float o01 = Tt[5] + Te[9]  + ob1;
        float o10 = Tt[6] + Te[10] + ob2;
        float o11 = Tt[7] + Te[11] + ob3;

        size_t p = (size_t)b * PAIRS_PER_B + q;
        out_cause[p * 2 + 0] = g0 * o00 + g1 * o10;
        out_cause[p * 2 + 1] = g0 * o01 + g1 * o11;
    }
}

// ---------------- launch ----------------
extern "C" void kernel_launch(void* const* d_in, const int* in_sizes, int n_in,
                              void* d_out, int out_size) {
    const float* pooled  = (const float*)d_in[0];
    const void*  spk     = d_in[1];
    const float* emo_w   = (const float*)d_in[2];
    const float* emo_b   = (const float*)d_in[3];
    const float* gate_w  = (const float*)d_in[4];
    const float* gate_b  = (const float*)d_in[5];
    const float* exp_w1  = (const float*)d_in[6];
    const float* exp_b1  = (const float*)d_in[7];
    const float* exp_w2  = (const float*)d_in[8];
    const float* exp_b2  = (const float*)d_in[9];
    float* out = (float*)d_out;

    fused_kernel<<<GRID, NTHR>>>(pooled, spk, emo_w, emo_b, gate_w, gate_b,
                                 exp_w1, exp_b1, exp_w2, exp_b2,
                                 out, out + ROWS * NE);
}

// round 11
// speedup vs baseline: 1.0243x; 1.0243x over previous
#include <cuda_runtime.h>
#include <cstdint>

// ---------------- problem constants ----------------
#define BB   16
#define DD   64
#define HH   768
#define NE   7
#define ROWS (BB*DD)                 // 1024 utterances
#define PAIRS_PER_B (DD*(DD+1)/2)    // 2080
#define NPAIR (BB*PAIRS_PER_B)       // 33280
#define FOLD_TASKS (2*1552)          // 3104

// ---------------- device scratch (no allocs allowed) ----------------
__device__ float g_Ob[4];             // folded expert bias [e*2+c]
__device__ float g_W19[19*HH];        // SoA packed weights [m][j]: m 0-6 emo |7-8 G1 |9-10 G2 |11-14 O1 |15-18 O2
__device__ float g_Tail[12*8];        // tail weights for f=768..775: [m][f-768] over the 12 T columns
__device__ float g_T[ROWS*12];        // per-utterance table [G1(2) G2(2) O1(4) O2(4)]
__device__ float g_spk[ROWS];         // speaker ids as float
__device__ unsigned short g_pairidx[PAIRS_PER_B]; // packed (end<<8)|t per in-batch pair q
__device__ unsigned int g_cnt[BB];    // per-batch monotonic sync counters (never reset)

// ================= kernel A: fold experts + pack weights + spk + pair LUT ===
// grid 400 x 256 = 3200 warps:
//   0..3103     : fold row (e,j) -> g_W19 / g_Tail
//   3104..3107  : Ob
//   3108        : speaker convert
//   3109..3119  : pack emo/gate into g_W19 SoA + gate tail
//   3120..3184  : pair index LUT (65 warps x 32 = 2080)
__global__ void __launch_bounds__(256)
prep_kernel(const void*  __restrict__ spk_raw,
            const float* __restrict__ emo_w,
            const float* __restrict__ gate_w,
            const float* __restrict__ w1,
            const float* __restrict__ b1,
            const float* __restrict__ w2,
            const float* __restrict__ b2) {
    const int gw   = (blockIdx.x * blockDim.x + threadIdx.x) >> 5;
    const int lane = threadIdx.x & 31;

    if (gw < FOLD_TASKS) {
        const int e = gw / 1552, j = gw - e * 1552;
        const float4* a4  = (const float4*)(w1 + ((size_t)(e * 1552 + j)) * 256);
        const float4* wb4 = (const float4*)(w2 + e * 512);
        float4 x0 = a4[lane];
        float4 x1 = a4[lane + 32];
        float4 p0 = wb4[2 * lane];
        float4 p1 = wb4[2 * lane + 1];
        float4 p2 = wb4[64 + 2 * lane];
        float4 p3 = wb4[65 + 2 * lane];
        float a0 = x0.x*p0.x + x0.y*p0.z + x0.z*p1.x + x0.w*p1.z
                 + x1.x*p2.x + x1.y*p2.z + x1.z*p3.x + x1.w*p3.z;
        float a1 = x0.x*p0.y + x0.y*p0.w + x0.z*p1.y + x0.w*p1.w
                 + x1.x*p2.y + x1.y*p2.w + x1.z*p3.y + x1.w*p3.w;
        #pragma unroll
        for (int off = 16; off; off >>= 1) {
            a0 += __shfl_down_sync(0xffffffffu, a0, off);
            a1 += __shfl_down_sync(0xffffffffu, a1, off);
        }
        if (lane == 0) {
            if (j < HH) {                          // first-half feature -> O1 (m = 11+e*2+c)
                g_W19[(11 + e * 2) * HH + j] = a0;
                g_W19[(12 + e * 2) * HH + j] = a1;
            } else if (j < 776) {                  // tail O1 feature: Tail m = 4+e*2+c
                g_Tail[(4 + e * 2) * 8 + (j - HH)] = a0;
                g_Tail[(5 + e * 2) * 8 + (j - HH)] = a1;
            } else if (j < 776 + HH) {             // second-half feature -> O2 (m = 15+e*2+c)
                int jj = j - 776;
                g_W19[(15 + e * 2) * HH + jj] = a0;
                g_W19[(16 + e * 2) * HH + jj] = a1;
            } else {                               // tail O2 feature: Tail m = 8+e*2+c
                g_Tail[(8 + e * 2) * 8 + (j - 776 - HH)] = a0;
                g_Tail[(9 + e * 2) * 8 + (j - 776 - HH)] = a1;
            }
        }
    } else if (gw < FOLD_TASKS + 4) {
        const int idx = gw - FOLD_TASKS;          // 0..3
        const int e = idx >> 1, c = idx & 1;
        float s = 0.f;
        for (int k = lane; k < 256; k += 32)
            s += b1[e * 256 + k] * w2[e * 512 + k * 2 + c];
        #pragma unroll
        for (int off = 16; off; off >>= 1)
            s += __shfl_down_sync(0xffffffffu, s, off);
        if (lane == 0) g_Ob[idx] = s + b2[e * 2 + c];
    } else if (gw == FOLD_TASKS + 4) {
        // speaker_ids stored int64 or int32 (values in {0,1}).
        // int64: odd 32-bit words of first 1024 words are all zero.
        const unsigned int* u = (const unsigned int*)spk_raw;
        unsigned nz = 0;
        for (int i = lane; i < ROWS; i += 32) nz |= u[2 * i + 1];
        unsigned any = __ballot_sync(0xffffffffu, nz != 0u);
        const bool w64 = (any == 0u);
        for (int i = lane; i < ROWS; i += 32)
            g_spk[i] = (float)(w64 ? u[2 * i] : u[i]);
    } else if (gw < FOLD_TASKS + 16) {
        // pack emo (5376) + G1 (1536) + G2 (1536) + gate tail (32) = 8480 elems
        const int pid = gw - (FOLD_TASKS + 5);    // 0..10
        for (int idx = pid * 32 + lane; idx < 8480; idx += 11 * 32) {
            if (idx < 5376) {
                int c = idx / HH, j = idx - c * HH;       // m = c
                g_W19[c * HH + j] = emo_w[j * 7 + c];
            } else if (idx < 5376 + 1536) {
                int q = idx - 5376;
                int c = q / HH, j = q - c * HH;           // m = 7+c
                g_W19[(7 + c) * HH + j] = gate_w[j * 2 + c];
            } else if (idx < 5376 + 3072) {
                int q = idx - 5376 - 1536;
                int c = q / HH, j = q - c * HH;           // m = 9+c
                g_W19[(9 + c) * HH + j] = gate_w[(776 + j) * 2 + c];
            } else {
                int q = idx - 5376 - 3072;                // 0..31
                int m = q >> 3, f8 = q & 7;
                int f = HH + f8;
                float v = (m < 2) ? gate_w[f * 2 + m]
                                  : gate_w[(776 + f) * 2 + (m - 2)];
                g_Tail[m * 8 + f8] = v;
            }
        }
    } else if (gw < FOLD_TASKS + 16 + 65) {
        // pair index LUT: q -> (end, t), end-major tril order
        const int q = (gw - (FOLD_TASKS + 16)) * 32 + lane;
        if (q < PAIRS_PER_B) {
            int end = (int)((sqrtf(8.f * (float)q + 1.f) - 1.f) * 0.5f);
            while ((end + 1) * (end + 2) / 2 <= q) end++;
            while (end * (end + 1) / 2 > q) end--;
            int t = q - end * (end + 1) / 2;
            g_pairidx[q] = (unsigned short)((end << 8) | t);
        }
    }

    // publish writes, then allow the PDL-dependent solve kernel to proceed
    __threadfence();
    cudaTriggerProgrammaticLaunchCompletion();
}

// ================= kernel B: table (1 row x 2 j-chunks per warp) + pairs ====
// Launched with programmatic-stream-serialization (PDL): starts while prep
// drains; prefetches x from DRAM, then cudaGridDependencySynchronize() gates
// all reads of prep's outputs (g_W19/g_Tail/g_spk/g_Ob/g_pairidx).
__global__ void __launch_bounds__(256, 2)
solve_kernel(const float* __restrict__ pooled,
             const float* __restrict__ emo_b,
             const float* __restrict__ gate_b,
             float* __restrict__ out_emo,     // [1024*7]
             float* __restrict__ out_cause) { // [33280*2]
    const int tid  = threadIdx.x;
    const int lane = tid & 31;
    const int warp = tid >> 5;
    const int base = blockIdx.x * 4;              // first row of this block
    const int b    = blockIdx.x >> 4;             // batch
    const int s    = blockIdx.x & 15;             // pair slice

    __shared__ float sp[4][2][20];                // [row_in_block][jchunk][m]

    const int row = warp >> 1;                    // 0..3
    const int jh  = warp & 1;                     // 0..1
    const int ti  = base + row;

    // ---- prefetch x (DRAM) BEFORE the dependency sync: overlaps prep tail --
    float4 x[3];
    {
        const float4* r = (const float4*)(pooled + (size_t)ti * HH);
        #pragma unroll
        for (int u = 0; u < 3; u++)
            x[u] = r[jh * 96 + u * 32 + lane];
    }

    // ---- wait for prep's outputs to be visible ----
    cudaGridDependencySynchronize();

    // ---- accumulate: warp = (row, j-chunk) ----
    {
        float acc[19];
        #pragma unroll
        for (int m = 0; m < 19; m++) acc[m] = 0.f;

        #pragma unroll
        for (int u = 0; u < 3; u++) {
            const int k = jh * 96 + u * 32 + lane;
            const float4 v = x[u];
            #pragma unroll
            for (int m = 0; m < 19; m++) {
                float4 w = __ldg((const float4*)(g_W19 + m * HH) + k);
                acc[m] += v.x*w.x + v.y*w.y + v.z*w.z + v.w*w.w;
            }
        }

        #pragma unroll
        for (int off = 16; off; off >>= 1) {
            #pragma unroll
            for (int m = 0; m < 19; m++)
                acc[m] += __shfl_down_sync(0xffffffffu, acc[m], off);
        }
        if (lane == 0) {
            #pragma unroll
            for (int m = 0; m < 19; m++)
                sp[row][jh][m] = acc[m];
        }
    }
    __syncthreads();

    // ---- finalize: warps 0-3, one row each, lanes = m ----
    if (warp < 4) {
        const int frow = warp;
        const int i = base + frow;
        float sacc = 0.f;
        if (lane < 19)
            sacc = sp[frow][0][lane] + sp[frow][1][lane];
        float ep = (lane < 7) ? sacc + emo_b[lane] : 0.f;

        // convergent broadcasts (all 32 lanes execute the same shfls)
        float epv[7];
        #pragma unroll
        for (int f8 = 0; f8 < 7; f8++)
            epv[f8] = __shfl_sync(0xffffffffu, ep, f8);

        if (lane < 7)
            out_emo[(size_t)i * 7 + lane] = ep;
        else if (lane < 19) {
            const int m = lane - 7;               // T column 0..11
            float v = sacc;
            #pragma unroll
            for (int f8 = 0; f8 < 7; f8++)
                v += epv[f8] * g_Tail[m * 8 + f8];
            v += g_spk[i] * g_Tail[m * 8 + 7];
            g_T[i * 12 + m] = v;
        }
    }

    // ---- per-batch sync (monotonic ticket; 16 blocks per counter) ----
    __syncthreads();
    if (tid == 0) {
        __threadfence();
        unsigned t = atomicAdd(&g_cnt[b], 1u) + 1u;
        unsigned round_end = ((t + 15u) / 16u) * 16u;
        volatile unsigned int* c = &g_cnt[b];
        while (*c < round_end) { __nanosleep(32); }
        __threadfence();
    }
    __syncthreads();

    // ---- pair phase: 130 pairs per block via LUT ----
    if (tid < 130) {
        const float gb0 = gate_b[0];
        const float gb1 = gate_b[1];
        const float ob0 = g_Ob[0], ob1 = g_Ob[1], ob2 = g_Ob[2], ob3 = g_Ob[3];
        const float* Tb = g_T + b * DD * 12;

        const int q = s * 130 + tid;              // 0..2079 within batch
        const unsigned pe = g_pairidx[q];
        const int end = pe >> 8;
        const int t   = pe & 255;

        const float* Tt = Tb + t   * 12;
        const float* Te = Tb + end * 12;

        float g0 = Tt[0] + Te[2] + gb0;
        float g1 = Tt[1] + Te[3] + gb1;

        float o00 = Tt[4] + Te[8]  + ob0;
        float o01 = Tt[5] + Te[9]  + ob1;
        float o10 = Tt[6] + Te[10] + ob2;
        float o11 = Tt[7] + Te[11] + ob3;

        size_t p = (size_t)b * PAIRS_PER_B + q;
        out_cause[p * 2 + 0] = g0 * o00 + g1 * o10;
        out_cause[p * 2 + 1] = g0 * o01 + g1 * o11;
    }
}

// ---------------- launch ----------------
extern "C" void kernel_launch(void* const* d_in, const int* in_sizes, int n_in,
                              void* d_out, int out_size) {
    const float* pooled  = (const float*)d_in[0];
    const void*  spk     = d_in[1];
    const float* emo_w   = (const float*)d_in[2];
    const float* emo_b   = (const float*)d_in[3];
    const float* gate_w  = (const float*)d_in[4];
    const float* gate_b  = (const float*)d_in[5];
    const float* exp_w1  = (const float*)d_in[6];
    const float* exp_b1  = (const float*)d_in[7];
    const float* exp_w2  = (const float*)d_in[8];
    const float* exp_b2  = (const float*)d_in[9];
    float* out = (float*)d_out;

    prep_kernel<<<400, 256>>>(spk, emo_w, gate_w, exp_w1, exp_b1, exp_w2, exp_b2);

    // PDL launch of solve: may start while prep drains; gated in-kernel by
    // cudaGridDependencySynchronize().
    cudaLaunchAttribute attrs[1];
    attrs[0].id = cudaLaunchAttributeProgrammaticStreamSerialization;
    attrs[0].val.programmaticStreamSerializationAllowed = 1;

    cudaLaunchConfig_t cfg = {};
    cfg.gridDim  = {256, 1, 1};
    cfg.blockDim = {256, 1, 1};
    cfg.dynamicSmemBytes = 0;
    cfg.stream = 0;                  // legacy default stream (same as <<<>>>)
    cfg.attrs = attrs;
    cfg.numAttrs = 1;

    cudaLaunchKernelEx(&cfg, solve_kernel,
                       pooled, emo_b, gate_b,
                       (float*)out, (float*)(out + ROWS * NE));
}

// round 12
// speedup vs baseline: 1.0261x; 1.0017x over previous
#include <cuda_runtime.h>
#include <cstdint>

// ---------------- problem constants ----------------
#define BB   16
#define DD   64
#define HH   768
#define NE   7
#define ROWS (BB*DD)                 // 1024 utterances
#define PAIRS_PER_B (DD*(DD+1)/2)    // 2080
#define NPAIR (BB*PAIRS_PER_B)       // 33280
#define FOLD_TASKS (2*1552)          // 3104

// ---------------- device scratch (no allocs allowed) ----------------
__device__ float g_Ob[4];             // folded expert bias [e*2+c]
__device__ float g_W19[19*HH];        // SoA packed weights [m][j]: m 0-6 emo |7-8 G1 |9-10 G2 |11-14 O1 |15-18 O2
__device__ float g_Tail[12*8];        // tail weights for f=768..775: [m][f-768] over the 12 T columns
__device__ float g_T[ROWS*12];        // per-utterance table [G1(2) G2(2) O1(4) O2(4)]
__device__ float g_spk[ROWS];         // speaker ids as float
__device__ unsigned short g_pairidx[PAIRS_PER_B]; // packed (end<<8)|t per in-batch pair q
__device__ unsigned int g_cnt[BB];    // per-batch monotonic sync counters (never reset)

// ================= kernel A: fold experts + pack weights + spk + pair LUT ===
// grid 400 x 256 = 3200 warps:
//   0..3103     : fold row (e,j) -> g_W19 / g_Tail
//   3104..3107  : Ob
//   3108        : speaker convert
//   3109..3119  : pack emo/gate into g_W19 SoA + gate tail
//   3120..3184  : pair index LUT (65 warps x 32 = 2080)
__global__ void __launch_bounds__(256)
prep_kernel(const void*  __restrict__ spk_raw,
            const float* __restrict__ emo_w,
            const float* __restrict__ gate_w,
            const float* __restrict__ w1,
            const float* __restrict__ b1,
            const float* __restrict__ w2,
            const float* __restrict__ b2) {
    const int gw   = (blockIdx.x * blockDim.x + threadIdx.x) >> 5;
    const int lane = threadIdx.x & 31;

    if (gw < FOLD_TASKS) {
        const int e = gw / 1552, j = gw - e * 1552;
        const float4* a4  = (const float4*)(w1 + ((size_t)(e * 1552 + j)) * 256);
        const float4* wb4 = (const float4*)(w2 + e * 512);
        float4 x0 = a4[lane];
        float4 x1 = a4[lane + 32];
        float4 p0 = wb4[2 * lane];
        float4 p1 = wb4[2 * lane + 1];
        float4 p2 = wb4[64 + 2 * lane];
        float4 p3 = wb4[65 + 2 * lane];
        float a0 = x0.x*p0.x + x0.y*p0.z + x0.z*p1.x + x0.w*p1.z
                 + x1.x*p2.x + x1.y*p2.z + x1.z*p3.x + x1.w*p3.z;
        float a1 = x0.x*p0.y + x0.y*p0.w + x0.z*p1.y + x0.w*p1.w
                 + x1.x*p2.y + x1.y*p2.w + x1.z*p3.y + x1.w*p3.w;
        #pragma unroll
        for (int off = 16; off; off >>= 1) {
            a0 += __shfl_down_sync(0xffffffffu, a0, off);
            a1 += __shfl_down_sync(0xffffffffu, a1, off);
        }
        if (lane == 0) {
            if (j < HH) {                          // first-half feature -> O1 (m = 11+e*2+c)
                g_W19[(11 + e * 2) * HH + j] = a0;
                g_W19[(12 + e * 2) * HH + j] = a1;
            } else if (j < 776) {                  // tail O1 feature: Tail m = 4+e*2+c
                g_Tail[(4 + e * 2) * 8 + (j - HH)] = a0;
                g_Tail[(5 + e * 2) * 8 + (j - HH)] = a1;
            } else if (j < 776 + HH) {             // second-half feature -> O2 (m = 15+e*2+c)
                int jj = j - 776;
                g_W19[(15 + e * 2) * HH + jj] = a0;
                g_W19[(16 + e * 2) * HH + jj] = a1;
            } else {                               // tail O2 feature: Tail m = 8+e*2+c
                g_Tail[(8 + e * 2) * 8 + (j - 776 - HH)] = a0;
                g_Tail[(9 + e * 2) * 8 + (j - 776 - HH)] = a1;
            }
        }
    } else if (gw < FOLD_TASKS + 4) {
        const int idx = gw - FOLD_TASKS;          // 0..3
        const int e = idx >> 1, c = idx & 1;
        float s = 0.f;
        for (int k = lane; k < 256; k += 32)
            s += b1[e * 256 + k] * w2[e * 512 + k * 2 + c];
        #pragma unroll
        for (int off = 16; off; off >>= 1)
            s += __shfl_down_sync(0xffffffffu, s, off);
        if (lane == 0) g_Ob[idx] = s + b2[e * 2 + c];
    } else if (gw == FOLD_TASKS + 4) {
        // speaker_ids stored int64 or int32 (values in {0,1}).
        // int64: odd 32-bit words of first 1024 words are all zero.
        const unsigned int* u = (const unsigned int*)spk_raw;
        unsigned nz = 0;
        for (int i = lane; i < ROWS; i += 32) nz |= u[2 * i + 1];
        unsigned any = __ballot_sync(0xffffffffu, nz != 0u);
        const bool w64 = (any == 0u);
        for (int i = lane; i < ROWS; i += 32)
            g_spk[i] = (float)(w64 ? u[2 * i] : u[i]);
    } else if (gw < FOLD_TASKS + 16) {
        // pack emo (5376) + G1 (1536) + G2 (1536) + gate tail (32) = 8480 elems
        const int pid = gw - (FOLD_TASKS + 5);    // 0..10
        for (int idx = pid * 32 + lane; idx < 8480; idx += 11 * 32) {
            if (idx < 5376) {
                int c = idx / HH, j = idx - c * HH;       // m = c
                g_W19[c * HH + j] = emo_w[j * 7 + c];
            } else if (idx < 5376 + 1536) {
                int q = idx - 5376;
                int c = q / HH, j = q - c * HH;           // m = 7+c
                g_W19[(7 + c) * HH + j] = gate_w[j * 2 + c];
            } else if (idx < 5376 + 3072) {
                int q = idx - 5376 - 1536;
                int c = q / HH, j = q - c * HH;           // m = 9+c
                g_W19[(9 + c) * HH + j] = gate_w[(776 + j) * 2 + c];
            } else {
                int q = idx - 5376 - 3072;                // 0..31
                int m = q >> 3, f8 = q & 7;
                int f = HH + f8;
                float v = (m < 2) ? gate_w[f * 2 + m]
                                  : gate_w[(776 + f) * 2 + (m - 2)];
                g_Tail[m * 8 + f8] = v;
            }
        }
    } else if (gw < FOLD_TASKS + 16 + 65) {
        // pair index LUT: q -> (end, t), end-major tril order
        const int q = (gw - (FOLD_TASKS + 16)) * 32 + lane;
        if (q < PAIRS_PER_B) {
            int end = (int)((sqrtf(8.f * (float)q + 1.f) - 1.f) * 0.5f);
            while ((end + 1) * (end + 2) / 2 <= q) end++;
            while (end * (end + 1) / 2 > q) end--;
            int t = q - end * (end + 1) / 2;
            g_pairidx[q] = (unsigned short)((end << 8) | t);
        }
    }
}

// ================= kernel B: table (m-split: warp = row x m-group) + pairs ==
// grid 512 x 256, launch_bounds(256,4) -> regs<=64 -> 592 residency slots,
// ENTIRE 512-block grid is wave-1 (per-batch spin sync trivially safe).
// Block = 2 rows. Warp w: row = w>>2, m-group mh = w&3 (m in [mh*5, mh*5+5),
// last group has 4). Each warp covers full j: 6 float4 per lane.
// Warp-reduce yields FINAL sums -> sp[row][m]; finalize warps 0-1.
// Per-batch sync: 32 blocks/counter. Pair phase: 65 pairs/block via LUT.
__global__ void __launch_bounds__(256, 4)
solve_kernel(const float* __restrict__ pooled,
             const float* __restrict__ emo_b,
             const float* __restrict__ gate_b,
             float* __restrict__ out_emo,     // [1024*7]
             float* __restrict__ out_cause) { // [33280*2]
    const int tid  = threadIdx.x;
    const int lane = tid & 31;
    const int warp = tid >> 5;
    const int base = blockIdx.x * 2;              // first row of this block
    const int b    = blockIdx.x >> 5;             // batch
    const int s    = blockIdx.x & 31;             // pair slice

    __shared__ float sp[2][20];                   // [row_in_block][m] final sums

    // ---- accumulate: warp = (row, m-group), full j per warp ----
    {
        const int row = warp >> 2;                // 0..1
        const int mh  = warp & 3;                 // 0..3
        const int m0  = mh * 5;
        const int nm  = (mh < 3) ? 5 : 4;
        const int i   = base + row;
        const float4* r = (const float4*)(pooled + (size_t)i * HH);

        // prefetch x (DRAM/L1) with full MLP: 6 float4 per lane
        float4 x[6];
        #pragma unroll
        for (int u = 0; u < 6; u++)
            x[u] = r[u * 32 + lane];

        float acc[5];
        #pragma unroll
        for (int mm = 0; mm < 5; mm++) acc[mm] = 0.f;

        #pragma unroll
        for (int u = 0; u < 6; u++) {
            const int k = u * 32 + lane;
            const float4 v = x[u];
            #pragma unroll
            for (int mm = 0; mm < 5; mm++) {
                if (mm < nm) {
                    float4 w = __ldg((const float4*)(g_W19 + (m0 + mm) * HH) + k);
                    acc[mm] += v.x*w.x + v.y*w.y + v.z*w.z + v.w*w.w;
                }
            }
        }

        #pragma unroll
        for (int off = 16; off; off >>= 1) {
            #pragma unroll
            for (int mm = 0; mm < 5; mm++)
                acc[mm] += __shfl_down_sync(0xffffffffu, acc[mm], off);
        }
        if (lane == 0) {
            #pragma unroll
            for (int mm = 0; mm < 5; mm++)
                if (mm < nm) sp[row][m0 + mm] = acc[mm];
        }
    }
    __syncthreads();

    // ---- finalize: warps 0-1, one row each, lanes = m (sums already final) --
    if (warp < 2) {
        const int row = warp;
        const int i = base + row;
        float sacc = (lane < 19) ? sp[row][lane] : 0.f;
        float ep = (lane < 7) ? sacc + emo_b[lane] : 0.f;

        // convergent broadcasts (all 32 lanes execute the same shfls)
        float epv[7];
        #pragma unroll
        for (int f8 = 0; f8 < 7; f8++)
            epv[f8] = __shfl_sync(0xffffffffu, ep, f8);

        if (lane < 7)
            out_emo[(size_t)i * 7 + lane] = ep;
        else if (lane < 19) {
            const int m = lane - 7;               // T column 0..11
            float v = sacc;
            #pragma unroll
            for (int f8 = 0; f8 < 7; f8++)
                v += epv[f8] * g_Tail[m * 8 + f8];
            v += g_spk[i] * g_Tail[m * 8 + 7];
            g_T[i * 12 + m] = v;
        }
    }

    // ---- per-batch sync (monotonic ticket; 32 blocks per counter) ----
    __syncthreads();
    if (tid == 0) {
        __threadfence();
        unsigned t = atomicAdd(&g_cnt[b], 1u) + 1u;
        unsigned round_end = ((t + 31u) / 32u) * 32u;
        volatile unsigned int* c = &g_cnt[b];
        while (*c < round_end) { __nanosleep(32); }
        __threadfence();
    }
    __syncthreads();

    // ---- pair phase: 65 pairs per block via LUT ----
    if (tid < 65) {
        const float gb0 = gate_b[0];
        const float gb1 = gate_b[1];
        const float ob0 = g_Ob[0], ob1 = g_Ob[1], ob2 = g_Ob[2], ob3 = g_Ob[3];
        const float* Tb = g_T + b * DD * 12;

        const int q = s * 65 + tid;               // 0..2079 within batch
        const unsigned pe = g_pairidx[q];
        const int end = pe >> 8;
        const int t   = pe & 255;

        const float* Tt = Tb + t   * 12;
        const float* Te = Tb + end * 12;

        float g0 = Tt[0] + Te[2] + gb0;
        float g1 = Tt[1] + Te[3] + gb1;

        float o00 = Tt[4] + Te[8]  + ob0;
        float o01 = Tt[5] + Te[9]  + ob1;
        float o10 = Tt[6] + Te[10] + ob2;
        float o11 = Tt[7] + Te[11] + ob3;

        size_t p = (size_t)b * PAIRS_PER_B + q;
        out_cause[p * 2 + 0] = g0 * o00 + g1 * o10;
        out_cause[p * 2 + 1] = g0 * o01 + g1 * o11;
    }
}

// ---------------- launch ----------------
extern "C" void kernel_launch(void* const* d_in, const int* in_sizes, int n_in,
                              void* d_out, int out_size) {
    const float* pooled  = (const float*)d_in[0];
    const void*  spk     = d_in[1];
    const float* emo_w   = (const float*)d_in[2];
    const float* emo_b   = (const float*)d_in[3];
    const float* gate_w  = (const float*)d_in[4];
    const float* gate_b  = (const float*)d_in[5];
    const float* exp_w1  = (const float*)d_in[6];
    const float* exp_b1  = (const float*)d_in[7];
    const float* exp_w2  = (const float*)d_in[8];
    const float* exp_b2  = (const float*)d_in[9];
    float* out = (float*)d_out;

    prep_kernel<<<400, 256>>>(spk, emo_w, gate_w, exp_w1, exp_b1, exp_w2, exp_b2);
    solve_kernel<<<512, 256>>>(pooled, emo_b, gate_b, out, out + ROWS * NE);
}

// round 13
// speedup vs baseline: 1.1090x; 1.0808x over previous
#include <cuda_runtime.h>
#include <cstdint>

// ---------------- problem constants ----------------
#define BB   16
#define DD   64
#define HH   768
#define NE   7
#define ROWS (BB*DD)                 // 1024 utterances
#define PAIRS_PER_B (DD*(DD+1)/2)    // 2080
#define NPAIR (BB*PAIRS_PER_B)       // 33280
#define FOLD_TASKS (2*1552)          // 3104

// ---------------- device scratch (no allocs allowed) ----------------
__device__ float g_Ob[4];             // folded expert bias [e*2+c]
__device__ float g_W19[19*HH];        // SoA packed weights [m][j]: m 0-6 emo |7-8 G1 |9-10 G2 |11-14 O1 |15-18 O2
__device__ float g_Tail[12*8];        // tail weights for f=768..775: [m][f-768] over the 12 T columns
__device__ float g_T[ROWS*12];        // per-utterance table [G1(2) G2(2) O1(4) O2(4)]
__device__ float g_spk[ROWS];         // speaker ids as float
__device__ unsigned short g_pairidx[PAIRS_PER_B]; // packed (end<<8)|t per in-batch pair q
__device__ unsigned int g_cnt[BB];    // per-batch monotonic sync counters (never reset)

// ================= kernel A: fold experts + pack weights + spk + pair LUT ===
__global__ void __launch_bounds__(256)
prep_kernel(const void*  __restrict__ spk_raw,
            const float* __restrict__ emo_w,
            const float* __restrict__ gate_w,
            const float* __restrict__ w1,
            const float* __restrict__ b1,
            const float* __restrict__ w2,
            const float* __restrict__ b2) {
    const int gw   = (blockIdx.x * blockDim.x + threadIdx.x) >> 5;
    const int lane = threadIdx.x & 31;

    if (gw < FOLD_TASKS) {
        const int e = gw / 1552, j = gw - e * 1552;
        const float4* a4  = (const float4*)(w1 + ((size_t)(e * 1552 + j)) * 256);
        const float4* wb4 = (const float4*)(w2 + e * 512);
        float4 x0 = a4[lane];
        float4 x1 = a4[lane + 32];
        float4 p0 = wb4[2 * lane];
        float4 p1 = wb4[2 * lane + 1];
        float4 p2 = wb4[64 + 2 * lane];
        float4 p3 = wb4[65 + 2 * lane];
        float a0 = x0.x*p0.x + x0.y*p0.z + x0.z*p1.x + x0.w*p1.z
                 + x1.x*p2.x + x1.y*p2.z + x1.z*p3.x + x1.w*p3.z;
        float a1 = x0.x*p0.y + x0.y*p0.w + x0.z*p1.y + x0.w*p1.w
                 + x1.x*p2.y + x1.y*p2.w + x1.z*p3.y + x1.w*p3.w;
        #pragma unroll
        for (int off = 16; off; off >>= 1) {
            a0 += __shfl_down_sync(0xffffffffu, a0, off);
            a1 += __shfl_down_sync(0xffffffffu, a1, off);
        }
        if (lane == 0) {
            if (j < HH) {                          // first-half feature -> O1 (m = 11+e*2+c)
                g_W19[(11 + e * 2) * HH + j] = a0;
                g_W19[(12 + e * 2) * HH + j] = a1;
            } else if (j < 776) {                  // tail O1 feature: Tail m = 4+e*2+c
                g_Tail[(4 + e * 2) * 8 + (j - HH)] = a0;
                g_Tail[(5 + e * 2) * 8 + (j - HH)] = a1;
            } else if (j < 776 + HH) {             // second-half feature -> O2 (m = 15+e*2+c)
                int jj = j - 776;
                g_W19[(15 + e * 2) * HH + jj] = a0;
                g_W19[(16 + e * 2) * HH + jj] = a1;
            } else {                               // tail O2 feature: Tail m = 8+e*2+c
                g_Tail[(8 + e * 2) * 8 + (j - 776 - HH)] = a0;
                g_Tail[(9 + e * 2) * 8 + (j - 776 - HH)] = a1;
            }
        }
    } else if (gw < FOLD_TASKS + 4) {
        const int idx = gw - FOLD_TASKS;          // 0..3
        const int e = idx >> 1, c = idx & 1;
        float s = 0.f;
        for (int k = lane; k < 256; k += 32)
            s += b1[e * 256 + k] * w2[e * 512 + k * 2 + c];
        #pragma unroll
        for (int off = 16; off; off >>= 1)
            s += __shfl_down_sync(0xffffffffu, s, off);
        if (lane == 0) g_Ob[idx] = s + b2[e * 2 + c];
    } else if (gw == FOLD_TASKS + 4) {
        // speaker_ids stored int64 or int32 (values in {0,1}).
        // int64: odd 32-bit words of first 1024 words are all zero.
        const unsigned int* u = (const unsigned int*)spk_raw;
        unsigned nz = 0;
        for (int i = lane; i < ROWS; i += 32) nz |= u[2 * i + 1];
        unsigned any = __ballot_sync(0xffffffffu, nz != 0u);
        const bool w64 = (any == 0u);
        for (int i = lane; i < ROWS; i += 32)
            g_spk[i] = (float)(w64 ? u[2 * i] : u[i]);
    } else if (gw < FOLD_TASKS + 16) {
        // pack emo (5376) + G1 (1536) + G2 (1536) + gate tail (32) = 8480 elems
        const int pid = gw - (FOLD_TASKS + 5);    // 0..10
        for (int idx = pid * 32 + lane; idx < 8480; idx += 11 * 32) {
            if (idx < 5376) {
                int c = idx / HH, j = idx - c * HH;       // m = c
                g_W19[c * HH + j] = emo_w[j * 7 + c];
            } else if (idx < 5376 + 1536) {
                int q = idx - 5376;
                int c = q / HH, j = q - c * HH;           // m = 7+c
                g_W19[(7 + c) * HH + j] = gate_w[j * 2 + c];
            } else if (idx < 5376 + 3072) {
                int q = idx - 5376 - 1536;
                int c = q / HH, j = q - c * HH;           // m = 9+c
                g_W19[(9 + c) * HH + j] = gate_w[(776 + j) * 2 + c];
            } else {
                int q = idx - 5376 - 3072;                // 0..31
                int m = q >> 3, f8 = q & 7;
                int f = HH + f8;
                float v = (m < 2) ? gate_w[f * 2 + m]
                                  : gate_w[(776 + f) * 2 + (m - 2)];
                g_Tail[m * 8 + f8] = v;
            }
        }
    } else if (gw < FOLD_TASKS + 16 + 65) {
        // pair index LUT: q -> (end, t), end-major tril order
        const int q = (gw - (FOLD_TASKS + 16)) * 32 + lane;
        if (q < PAIRS_PER_B) {
            int end = (int)((sqrtf(8.f * (float)q + 1.f) - 1.f) * 0.5f);
            while ((end + 1) * (end + 2) / 2 <= q) end++;
            while (end * (end + 1) / 2 > q) end--;
            int t = q - end * (end + 1) / 2;
            g_pairidx[q] = (unsigned short)((end << 8) | t);
        }
    }
}

// ================= kernel B: 4-row weight reuse + smem-x + pairs ============
// grid 128 x 256: block = 8 contiguous rows, x staged to smem (24KB linear
// copy). Warp w = (row-quad rq = w>>2, m-group mg = w&3; m in [mg*5,mg*5+nm)).
// Per j-chunk: load nm weight float4 ONCE (registers), reuse across 4 rows
// read from smem (crossbar, not L1tex). Weight L1 traffic: 58KB per row-quad
// instead of per row -> 4x reduction (14.8MB vs 60MB chip-wide).
// Finalize: warps 0-7, one row each. Per-batch sync: 8 blocks/counter.
// Pair phase: 260 pairs per block via LUT.
__global__ void __launch_bounds__(256, 2)
solve_kernel(const float* __restrict__ pooled,
             const float* __restrict__ emo_b,
             const float* __restrict__ gate_b,
             float* __restrict__ out_emo,     // [1024*7]
             float* __restrict__ out_cause) { // [33280*2]
    __shared__ float4 sx[8 * 192];            // 8 rows x 192 float4 = 24KB
    __shared__ float  spacc[8][20];           // [row_in_block][m] final sums

    const int tid  = threadIdx.x;
    const int lane = tid & 31;
    const int warp = tid >> 5;
    const int base = blockIdx.x * 8;          // first row of this block
    const int b    = blockIdx.x >> 3;         // batch
    const int s    = blockIdx.x & 7;          // pair slice

    // ---- stage x: 8 contiguous rows = 1536 float4, linear copy, MLP=6 ----
    {
        const float4* p4 = (const float4*)pooled + (size_t)base * 192;
        #pragma unroll 6
        for (int idx = tid; idx < 1536; idx += 256)
            sx[idx] = p4[idx];
    }
    __syncthreads();

    // ---- accumulate: warp = (row-quad, m-group), weights reused x4 rows ----
    {
        const int rq = warp >> 2;             // 0..1
        const int mg = warp & 3;              // 0..3
        const int m0 = mg * 5;
        const int nm = (mg < 3) ? 5 : 4;
        const float4* gW4 = (const float4*)g_W19;

        float acc[4][5];
        #pragma unroll
        for (int rr = 0; rr < 4; rr++)
            #pragma unroll
            for (int mm = 0; mm < 5; mm++) acc[rr][mm] = 0.f;

        #pragma unroll
        for (int u = 0; u < 6; u++) {
            const int k = u * 32 + lane;      // float4 index 0..191
            float4 w[5];
            #pragma unroll
            for (int mm = 0; mm < 5; mm++)
                if (mm < nm) w[mm] = __ldg(gW4 + (m0 + mm) * 192 + k);
            #pragma unroll
            for (int rr = 0; rr < 4; rr++) {
                const float4 xv = sx[(rq * 4 + rr) * 192 + k];
                #pragma unroll
                for (int mm = 0; mm < 5; mm++) {
                    if (mm < nm)
                        acc[rr][mm] += xv.x * w[mm].x + xv.y * w[mm].y
                                     + xv.z * w[mm].z + xv.w * w[mm].w;
                }
            }
        }

        // reduce 20 sums across the warp
        #pragma unroll
        for (int off = 16; off; off >>= 1) {
            #pragma unroll
            for (int rr = 0; rr < 4; rr++)
                #pragma unroll
                for (int mm = 0; mm < 5; mm++)
                    acc[rr][mm] += __shfl_down_sync(0xffffffffu, acc[rr][mm], off);
        }
        if (lane == 0) {
            #pragma unroll
            for (int rr = 0; rr < 4; rr++)
                #pragma unroll
                for (int mm = 0; mm < 5; mm++)
                    if (mm < nm) spacc[rq * 4 + rr][m0 + mm] = acc[rr][mm];
        }
    }
    __syncthreads();

    // ---- finalize: warps 0-7, one row each, lanes = m (sums final) ----
    {
        const int row = warp;                 // 0..7
        const int i = base + row;
        float sacc = (lane < 19) ? spacc[row][lane] : 0.f;
        float ep = (lane < 7) ? sacc + emo_b[lane] : 0.f;

        // convergent broadcasts (all 32 lanes execute the same shfls)
        float epv[7];
        #pragma unroll
        for (int f8 = 0; f8 < 7; f8++)
            epv[f8] = __shfl_sync(0xffffffffu, ep, f8);

        if (lane < 7)
            out_emo[(size_t)i * 7 + lane] = ep;
        else if (lane < 19) {
            const int m = lane - 7;           // T column 0..11
            float v = sacc;
            #pragma unroll
            for (int f8 = 0; f8 < 7; f8++)
                v += epv[f8] * g_Tail[m * 8 + f8];
            v += g_spk[i] * g_Tail[m * 8 + 7];
            g_T[i * 12 + m] = v;
        }
    }

    // ---- per-batch sync (monotonic ticket; 8 blocks per counter) ----
    // 128 blocks <= 148 SMs -> entire grid wave-1 resident, spin is safe.
    __syncthreads();
    if (tid == 0) {
        __threadfence();
        unsigned t = atomicAdd(&g_cnt[b], 1u) + 1u;
        unsigned round_end = ((t + 7u) / 8u) * 8u;
        volatile unsigned int* c = &g_cnt[b];
        while (*c < round_end) { __nanosleep(32); }
        __threadfence();
    }
    __syncthreads();

    // ---- pair phase: 260 pairs per block via LUT ----
    const float gb0 = gate_b[0];
    const float gb1 = gate_b[1];
    const float ob0 = g_Ob[0], ob1 = g_Ob[1], ob2 = g_Ob[2], ob3 = g_Ob[3];
    const float* Tb = g_T + b * DD * 12;

    for (int ql = tid; ql < 260; ql += 256) {
        const int q = s * 260 + ql;           // 0..2079 within batch
        const unsigned pe = g_pairidx[q];
        const int end = pe >> 8;
        const int t   = pe & 255;

        const float* Tt = Tb + t   * 12;
        const float* Te = Tb + end * 12;

        float g0 = Tt[0] + Te[2] + gb0;
        float g1 = Tt[1] + Te[3] + gb1;

        float o00 = Tt[4] + Te[8]  + ob0;
        float o01 = Tt[5] + Te[9]  + ob1;
        float o10 = Tt[6] + Te[10] + ob2;
        float o11 = Tt[7] + Te[11] + ob3;

        size_t p = (size_t)b * PAIRS_PER_B + q;
        out_cause[p * 2 + 0] = g0 * o00 + g1 * o10;
        out_cause[p * 2 + 1] = g0 * o01 + g1 * o11;
    }
}

// ---------------- launch ----------------
extern "C" void kernel_launch(void* const* d_in, const int* in_sizes, int n_in,
                              void* d_out, int out_size) {
    const float* pooled  = (const float*)d_in[0];
    const void*  spk     = d_in[1];
    const float* emo_w   = (const float*)d_in[2];
    const float* emo_b   = (const float*)d_in[3];
    const float* gate_w  = (const float*)d_in[4];
    const float* gate_b  = (const float*)d_in[5];
    const float* exp_w1  = (const float*)d_in[6];
    const float* exp_b1  = (const float*)d_in[7];
    const float* exp_w2  = (const float*)d_in[8];
    const float* exp_b2  = (const float*)d_in[9];
    float* out = (float*)d_out;

    prep_kernel<<<400, 256>>>(spk, emo_w, gate_w, exp_w1, exp_b1, exp_w2, exp_b2);
    solve_kernel<<<128, 256>>>(pooled, emo_b, gate_b, out, out + ROWS * NE);
}

// round 15
// speedup vs baseline: 1.1260x; 1.0153x over previous
#include <cuda_runtime.h>
#include <cstdint>

// ---------------- problem constants ----------------
#define BB   16
#define DD   64
#define HH   768
#define NE   7
#define ROWS (BB*DD)                 // 1024 utterances
#define PAIRS_PER_B (DD*(DD+1)/2)    // 2080
#define NPAIR (BB*PAIRS_PER_B)       // 33280
#define FOLD_TASKS (2*1552)          // 3104
#define LUT_W  65                    // pair-LUT warps
#define PF_W   96                    // pooled-prefetch warps
#define PACK_ELEMS (8480 + HH)       // 9248: emo+G1+G2+gate-tail+zero-pad row

// ---------------- device scratch (no allocs allowed) ----------------
__device__ float g_Ob[4];             // folded expert bias [e*2+c]
__device__ float g_W19[20*HH];        // SoA packed weights [m][j], m=19 is a ZERO pad row
__device__ float g_Tail[12*8];        // tail weights for f=768..775: [m][f-768] over the 12 T columns
__device__ float g_T[ROWS*12];        // per-utterance table [G1(2) G2(2) O1(4) O2(4)]
__device__ float g_spk[ROWS];         // speaker ids as float
__device__ unsigned short g_pairidx[PAIRS_PER_B]; // packed (end<<8)|t per in-batch pair q
__device__ unsigned int g_cnt[BB];    // per-batch monotonic sync counters (never reset)

// ================= kernel A: fold + pack + spk + LUT + pooled L2 prefetch ===
__global__ void __launch_bounds__(256)
prep_kernel(const void*  __restrict__ spk_raw,
            const float* __restrict__ emo_w,
            const float* __restrict__ gate_w,
            const float* __restrict__ w1,
            const float* __restrict__ b1,
            const float* __restrict__ w2,
            const float* __restrict__ b2,
            const float* __restrict__ pooled) {
    const int gw   = (blockIdx.x * blockDim.x + threadIdx.x) >> 5;
    const int lane = threadIdx.x & 31;

    if (gw < FOLD_TASKS) {
        const int e = gw / 1552, j = gw - e * 1552;
        const float4* a4  = (const float4*)(w1 + ((size_t)(e * 1552 + j)) * 256);
        const float4* wb4 = (const float4*)(w2 + e * 512);
        float4 x0 = a4[lane];
        float4 x1 = a4[lane + 32];
        float4 p0 = wb4[2 * lane];
        float4 p1 = wb4[2 * lane + 1];
        float4 p2 = wb4[64 + 2 * lane];
        float4 p3 = wb4[65 + 2 * lane];
        float a0 = x0.x*p0.x + x0.y*p0.z + x0.z*p1.x + x0.w*p1.z
                 + x1.x*p2.x + x1.y*p2.z + x1.z*p3.x + x1.w*p3.z;
        float a1 = x0.x*p0.y + x0.y*p0.w + x0.z*p1.y + x0.w*p1.w
                 + x1.x*p2.y + x1.y*p2.w + x1.z*p3.y + x1.w*p3.w;
        #pragma unroll
        for (int off = 16; off; off >>= 1) {
            a0 += __shfl_down_sync(0xffffffffu, a0, off);
            a1 += __shfl_down_sync(0xffffffffu, a1, off);
        }
        if (lane == 0) {
            if (j < HH) {                          // first-half feature -> O1 (m = 11+e*2+c)
                g_W19[(11 + e * 2) * HH + j] = a0;
                g_W19[(12 + e * 2) * HH + j] = a1;
            } else if (j < 776) {                  // tail O1 feature: Tail m = 4+e*2+c
                g_Tail[(4 + e * 2) * 8 + (j - HH)] = a0;
                g_Tail[(5 + e * 2) * 8 + (j - HH)] = a1;
            } else if (j < 776 + HH) {             // second-half feature -> O2 (m = 15+e*2+c)
                int jj = j - 776;
                g_W19[(15 + e * 2) * HH + jj] = a0;
                g_W19[(16 + e * 2) * HH + jj] = a1;
            } else {                               // tail O2 feature: Tail m = 8+e*2+c
                g_Tail[(8 + e * 2) * 8 + (j - 776 - HH)] = a0;
                g_Tail[(9 + e * 2) * 8 + (j - 776 - HH)] = a1;
            }
        }
    } else if (gw < FOLD_TASKS + 4) {
        const int idx = gw - FOLD_TASKS;          // 0..3
        const int e = idx >> 1, c = idx & 1;
        float s = 0.f;
        for (int k = lane; k < 256; k += 32)
            s += b1[e * 256 + k] * w2[e * 512 + k * 2 + c];
        #pragma unroll
        for (int off = 16; off; off >>= 1)
            s += __shfl_down_sync(0xffffffffu, s, off);
        if (lane == 0) g_Ob[idx] = s + b2[e * 2 + c];
    } else if (gw == FOLD_TASKS + 4) {
        // speaker_ids stored int64 or int32 (values in {0,1}).
        // int64: odd 32-bit words of first 1024 words are all zero.
        const unsigned int* u = (const unsigned int*)spk_raw;
        unsigned nz = 0;
        for (int i = lane; i < ROWS; i += 32) nz |= u[2 * i + 1];
        unsigned any = __ballot_sync(0xffffffffu, nz != 0u);
        const bool w64 = (any == 0u);
        for (int i = lane; i < ROWS; i += 32)
            g_spk[i] = (float)(w64 ? u[2 * i] : u[i]);
    } else if (gw < FOLD_TASKS + 16) {
        // pack emo (5376) + G1 (1536) + G2 (1536) + gate tail (32)
        //    + zero pad row m=19 (768) = 9248 elems  (NOT more: OOB guard!)
        const int pid = gw - (FOLD_TASKS + 5);    // 0..10
        for (int idx = pid * 32 + lane; idx < PACK_ELEMS; idx += 11 * 32) {
            if (idx < 5376) {
                int c = idx / HH, j = idx - c * HH;       // m = c
                g_W19[c * HH + j] = emo_w[j * 7 + c];
            } else if (idx < 5376 + 1536) {
                int q = idx - 5376;
                int c = q / HH, j = q - c * HH;           // m = 7+c
                g_W19[(7 + c) * HH + j] = gate_w[j * 2 + c];
            } else if (idx < 5376 + 3072) {
                int q = idx - 5376 - 1536;
                int c = q / HH, j = q - c * HH;           // m = 9+c
                g_W19[(9 + c) * HH + j] = gate_w[(776 + j) * 2 + c];
            } else if (idx < 5376 + 3072 + 32) {
                int q = idx - 5376 - 3072;                // 0..31
                int m = q >> 3, f8 = q & 7;
                int f = HH + f8;
                float v = (m < 2) ? gate_w[f * 2 + m]
                                  : gate_w[(776 + f) * 2 + (m - 2)];
                g_Tail[m * 8 + f8] = v;
            } else {
                int j = idx - 8480;                       // 0..767: zero pad row
                g_W19[19 * HH + j] = 0.f;
            }
        }
    } else if (gw < FOLD_TASKS + 16 + LUT_W) {
        // pair index LUT: q -> (end, t), end-major tril order
        const int q = (gw - (FOLD_TASKS + 16)) * 32 + lane;
        if (q < PAIRS_PER_B) {
            int end = (int)((sqrtf(8.f * (float)q + 1.f) - 1.f) * 0.5f);
            while ((end + 1) * (end + 2) / 2 <= q) end++;
            while (end * (end + 1) / 2 > q) end--;
            int t = q - end * (end + 1) / 2;
            g_pairidx[q] = (unsigned short)((end << 8) | t);
        }
    } else if (gw < FOLD_TASKS + 16 + LUT_W + PF_W) {
        // L2-prefetch the 3MB pooled matrix so solve's x staging hits L2.
        const int pw = gw - (FOLD_TASKS + 16 + LUT_W);    // 0..95
        const int lg = pw * 32 + lane;                    // 0..3071
        #pragma unroll
        for (int it = 0; it < 8; it++) {
            const float* addr = pooled + (size_t)(lg + 3072 * it) * 32; // 128B lines
            asm volatile("prefetch.global.L2 [%0];" :: "l"(addr));
        }
    }
}

// ================= kernel B: 4-row weight reuse + smem-x + pairs ============
// grid 128 x 256: block = 8 contiguous rows, x staged to smem (24KB).
// Warp w = (row-quad rq = w>>2, m-group mg = w&3; m in [mg*5, mg*5+5)),
// m=19 is a zero pad row -> NO conditionals in the hot loop.
__global__ void __launch_bounds__(256, 2)
solve_kernel(const float* __restrict__ pooled,
             const float* __restrict__ emo_b,
             const float* __restrict__ gate_b,
             float* __restrict__ out_emo,     // [1024*7]
             float* __restrict__ out_cause) { // [33280*2]
    __shared__ float4 sx[8 * 192];            // 8 rows x 192 float4 = 24KB
    __shared__ float  spacc[8][20];           // [row_in_block][m] final sums

    const int tid  = threadIdx.x;
    const int lane = tid & 31;
    const int warp = tid >> 5;
    const int base = blockIdx.x * 8;          // first row of this block
    const int b    = blockIdx.x >> 3;         // batch
    const int s    = blockIdx.x & 7;          // pair slice

    // ---- stage x: 8 contiguous rows = 1536 float4, linear copy (L2 hits) ---
    {
        const float4* p4 = (const float4*)pooled + (size_t)base * 192;
        #pragma unroll 6
        for (int idx = tid; idx < 1536; idx += 256)
            sx[idx] = p4[idx];
    }
    __syncthreads();

    // ---- accumulate: warp = (row-quad, m-group), weights reused x4 rows ----
    {
        const int rq = warp >> 2;             // 0..1
        const int mg = warp & 3;              // 0..3
        const int m0 = mg * 5;
        const float4* gW4 = (const float4*)g_W19;

        float acc[4][5];
        #pragma unroll
        for (int rr = 0; rr < 4; rr++)
            #pragma unroll
            for (int mm = 0; mm < 5; mm++) acc[rr][mm] = 0.f;

        #pragma unroll
        for (int u = 0; u < 6; u++) {
            const int k = u * 32 + lane;      // float4 index 0..191
            float4 w[5];
            #pragma unroll
            for (int mm = 0; mm < 5; mm++)
                w[mm] = __ldg(gW4 + (m0 + mm) * 192 + k);
            #pragma unroll
            for (int rr = 0; rr < 4; rr++) {
                const float4 xv = sx[(rq * 4 + rr) * 192 + k];
                #pragma unroll
                for (int mm = 0; mm < 5; mm++)
                    acc[rr][mm] += xv.x * w[mm].x + xv.y * w[mm].y
                                 + xv.z * w[mm].z + xv.w * w[mm].w;
            }
        }

        // reduce 20 sums across the warp
        #pragma unroll
        for (int off = 16; off; off >>= 1) {
            #pragma unroll
            for (int rr = 0; rr < 4; rr++)
                #pragma unroll
                for (int mm = 0; mm < 5; mm++)
                    acc[rr][mm] += __shfl_down_sync(0xffffffffu, acc[rr][mm], off);
        }
        if (lane == 0) {
            #pragma unroll
            for (int rr = 0; rr < 4; rr++)
                #pragma unroll
                for (int mm = 0; mm < 5; mm++)
                    spacc[rq * 4 + rr][m0 + mm] = acc[rr][mm];
        }
    }
    __syncthreads();

    // ---- finalize: warps 0-7, one row each, lanes = m (sums final) ----
    {
        const int row = warp;                 // 0..7
        const int i = base + row;
        float sacc = (lane < 19) ? spacc[row][lane] : 0.f;
        float ep = (lane < 7) ? sacc + emo_b[lane] : 0.f;

        // convergent broadcasts (all 32 lanes execute the same shfls)
        float epv[7];
        #pragma unroll
        for (int f8 = 0; f8 < 7; f8++)
            epv[f8] = __shfl_sync(0xffffffffu, ep, f8);

        if (lane < 7)
            out_emo[(size_t)i * 7 + lane] = ep;
        else if (lane < 19) {
            const int m = lane - 7;           // T column 0..11
            float v = sacc;
            #pragma unroll
            for (int f8 = 0; f8 < 7; f8++)
                v += epv[f8] * g_Tail[m * 8 + f8];
            v += g_spk[i] * g_Tail[m * 8 + 7];
            g_T[i * 12 + m] = v;
        }
    }

    // ---- per-batch sync (monotonic ticket; 8 blocks per counter) ----
    // 128 blocks <= 148 SMs -> entire grid wave-1 resident, spin is safe.
    __syncthreads();
    if (tid == 0) {
        __threadfence();
        unsigned t = atomicAdd(&g_cnt[b], 1u) + 1u;
        unsigned round_end = ((t + 7u) / 8u) * 8u;
        volatile unsigned int* c = &g_cnt[b];
        while (*c < round_end) { __nanosleep(32); }
        __threadfence();
    }
    __syncthreads();

    // ---- pair phase: 260 pairs per block, 2 pairs/thread, float4 stores ----
    if (tid < 130) {
        const float gb0 = gate_b[0];
        const float gb1 = gate_b[1];
        const float ob0 = g_Ob[0], ob1 = g_Ob[1], ob2 = g_Ob[2], ob3 = g_Ob[3];
        const float* Tb = g_T + b * DD * 12;

        const int q0 = s * 260 + tid * 2;     // even; q0,q0+1 within batch
        float4 res;
        {
            const unsigned pe = g_pairidx[q0];
            const float* Tt = Tb + (pe & 255) * 12;
            const float* Te = Tb + (pe >> 8) * 12;
            float g0 = Tt[0] + Te[2] + gb0;
            float g1 = Tt[1] + Te[3] + gb1;
            res.x = g0 * (Tt[4] + Te[8]  + ob0) + g1 * (Tt[6] + Te[10] + ob2);
            res.y = g0 * (Tt[5] + Te[9]  + ob1) + g1 * (Tt[7] + Te[11] + ob3);
        }
        {
            const unsigned pe = g_pairidx[q0 + 1];
            const float* Tt = Tb + (pe & 255) * 12;
            const float* Te = Tb + (pe >> 8) * 12;
            float g0 = Tt[0] + Te[2] + gb0;
            float g1 = Tt[1] + Te[3] + gb1;
            res.z = g0 * (Tt[4] + Te[8]  + ob0) + g1 * (Tt[6] + Te[10] + ob2);
            res.w = g0 * (Tt[5] + Te[9]  + ob1) + g1 * (Tt[7] + Te[11] + ob3);
        }
        const size_t p0 = (size_t)b * PAIRS_PER_B + q0;   // even
        *(float4*)(out_cause + p0 * 2) = res;
    }
}

// ---------------- launch ----------------
extern "C" void kernel_launch(void* const* d_in, const int* in_sizes, int n_in,
                              void* d_out, int out_size) {
    const float* pooled  = (const float*)d_in[0];
    const void*  spk     = d_in[1];
    const float* emo_w   = (const float*)d_in[2];
    const float* emo_b   = (const float*)d_in[3];
    const float* gate_w  = (const float*)d_in[4];
    const float* gate_b  = (const float*)d_in[5];
    const float* exp_w1  = (const float*)d_in[6];
    const float* exp_b1  = (const float*)d_in[7];
    const float* exp_w2  = (const float*)d_in[8];
    const float* exp_b2  = (const float*)d_in[9];
    float* out = (float*)d_out;

    prep_kernel<<<411, 256>>>(spk, emo_w, gate_w, exp_w1, exp_b1, exp_w2, exp_b2, pooled);
    solve_kernel<<<128, 256>>>(pooled, emo_b, gate_b, out, out + ROWS * NE);
}